// round 1
// baseline (speedup 1.0000x reference)
#include <cuda_runtime.h>
#include <cstdint>
#include <cstddef>

// ---------------------------------------------------------------------------
// AttnBlock: GroupNorm -> QKV (1x1 conv GEMMs) -> softmax attention -> proj+res
// Shapes: b=32, c=512, n=h*w=1024, groups=16
// ---------------------------------------------------------------------------

#define BATCH 32
#define CCH   512
#define NTOK  1024
#define NGRP  16
#define CPG   (CCH / NGRP)          // 32 channels per group
#define GSIZE (CPG * NTOK)          // 32768 elems per group

// Scratch (device globals: allocation-free per harness rules)
__device__ float g_hn[(size_t)BATCH * CCH * NTOK];   // 64 MB
__device__ float g_q [(size_t)BATCH * CCH * NTOK];
__device__ float g_k [(size_t)BATCH * CCH * NTOK];
__device__ float g_v [(size_t)BATCH * CCH * NTOK];
__device__ float g_o [(size_t)BATCH * CCH * NTOK];
__device__ float g_s [(size_t)BATCH * NTOK * NTOK]; // 128 MB

// ---------------------------------------------------------------------------
// GroupNorm: one block per (group, batch). Two passes over 32K floats (L2-hot).
// ---------------------------------------------------------------------------
__global__ void __launch_bounds__(256) gn_kernel(
    const float* __restrict__ x, const float* __restrict__ gamma,
    const float* __restrict__ beta, float* __restrict__ hn)
{
    const int g = blockIdx.x, b = blockIdx.y;
    const size_t base = ((size_t)b * CCH + (size_t)g * CPG) * NTOK;
    const float4* xp = reinterpret_cast<const float4*>(x + base);
    float4*       hp = reinterpret_cast<float4*>(hn + base);
    const int tid = threadIdx.x;

    float s = 0.f, ss = 0.f;
    for (int i = tid; i < GSIZE / 4; i += 256) {
        float4 v = xp[i];
        s  += v.x + v.y + v.z + v.w;
        ss += v.x * v.x + v.y * v.y + v.z * v.z + v.w * v.w;
    }
    __shared__ float rs[256], rss[256];
    rs[tid] = s; rss[tid] = ss;
    __syncthreads();
    for (int w = 128; w > 0; w >>= 1) {
        if (tid < w) { rs[tid] += rs[tid + w]; rss[tid] += rss[tid + w]; }
        __syncthreads();
    }
    const float mean = rs[0] * (1.f / GSIZE);
    const float var  = rss[0] * (1.f / GSIZE) - mean * mean;
    const float rstd = rsqrtf(var + 1e-6f);

    for (int i = tid; i < GSIZE / 4; i += 256) {
        const int c = g * CPG + (i >> 8);          // (i*4)/1024
        const float ga = gamma[c] * rstd;
        const float be = beta[c] - mean * ga;
        float4 v = xp[i];
        v.x = v.x * ga + be; v.y = v.y * ga + be;
        v.z = v.z * ga + be; v.w = v.w * ga + be;
        hp[i] = v;
    }
}

// ---------------------------------------------------------------------------
// Templated SGEMM, 64x64x16 tile, 256 threads, 4x4 microtile.
//   AMODE 0: A is MxK row-major (A[i*K+k]);  1: A is KxM (A[k*M+i])
//   BMODE 0: B is KxN (B[k*N+j]);            1: B is NxK (B[j*K+k])
// C is MxN row-major. Optional bias[i] and residual (same layout as C).
// M,N,K must be multiples of 64/16 (true here: 512/1024).
// ---------------------------------------------------------------------------
template<int AMODE, int BMODE, bool BIAS, bool RESID>
__global__ void __launch_bounds__(256) gemm_kernel(
    const float* __restrict__ A, const float* __restrict__ B,
    const float* __restrict__ bias, const float* __restrict__ resid,
    float* __restrict__ C,
    int M, int N, int K,
    size_t sA, size_t sB, size_t sC, size_t sR, float scale)
{
    const int z = blockIdx.z;
    A += (size_t)z * sA;
    B += (size_t)z * sB;
    C += (size_t)z * sC;
    if (RESID) resid += (size_t)z * sR;

    const int n0 = blockIdx.x * 64, m0 = blockIdx.y * 64;
    const int tid = threadIdx.x;
    const int tx = tid & 15, ty = tid >> 4;

    // 68-float rows: row pitch 272B is 16B-aligned -> float4 smem ld/st legal.
    __shared__ float As[16 * 68];
    __shared__ float Bs[16 * 68];

    float acc[4][4] = {};

    for (int k0 = 0; k0 < K; k0 += 16) {
        // ---- load A tile into As[kk][m] ----
        if (AMODE == 0) {
            const int row = tid >> 2, kc = (tid & 3) * 4;
            const float4 a = *reinterpret_cast<const float4*>(
                &A[(size_t)(m0 + row) * K + k0 + kc]);
            As[(kc + 0) * 68 + row] = a.x;
            As[(kc + 1) * 68 + row] = a.y;
            As[(kc + 2) * 68 + row] = a.z;
            As[(kc + 3) * 68 + row] = a.w;
        } else {
            const int kk = tid >> 4, mc = (tid & 15) * 4;
            *reinterpret_cast<float4*>(&As[kk * 68 + mc]) =
                *reinterpret_cast<const float4*>(&A[(size_t)(k0 + kk) * M + m0 + mc]);
        }
        // ---- load B tile into Bs[kk][n] ----
        if (BMODE == 0) {
            const int kk = tid >> 4, nc = (tid & 15) * 4;
            *reinterpret_cast<float4*>(&Bs[kk * 68 + nc]) =
                *reinterpret_cast<const float4*>(&B[(size_t)(k0 + kk) * N + n0 + nc]);
        } else {
            const int row = tid >> 2, kc = (tid & 3) * 4;
            const float4 b4 = *reinterpret_cast<const float4*>(
                &B[(size_t)(n0 + row) * K + k0 + kc]);
            Bs[(kc + 0) * 68 + row] = b4.x;
            Bs[(kc + 1) * 68 + row] = b4.y;
            Bs[(kc + 2) * 68 + row] = b4.z;
            Bs[(kc + 3) * 68 + row] = b4.w;
        }
        __syncthreads();

        #pragma unroll
        for (int kk = 0; kk < 16; kk++) {
            const float4 a = *reinterpret_cast<const float4*>(&As[kk * 68 + ty * 4]);
            const float4 b = *reinterpret_cast<const float4*>(&Bs[kk * 68 + tx * 4]);
            const float av[4] = {a.x, a.y, a.z, a.w};
            const float bv[4] = {b.x, b.y, b.z, b.w};
            #pragma unroll
            for (int i = 0; i < 4; i++)
                #pragma unroll
                for (int j = 0; j < 4; j++)
                    acc[i][j] += av[i] * bv[j];
        }
        __syncthreads();
    }

    #pragma unroll
    for (int i = 0; i < 4; i++) {
        const int row = m0 + ty * 4 + i;
        const float bv = BIAS ? bias[row] : 0.f;
        #pragma unroll
        for (int j = 0; j < 4; j++) {
            const int col = n0 + tx * 4 + j;
            float v = acc[i][j] * scale + bv;
            if (RESID) v += resid[(size_t)row * N + col];
            C[(size_t)row * N + col] = v;
        }
    }
}

// ---------------------------------------------------------------------------
// Row softmax over m for s[b][n][m]; shift-invariance makes per-row max
// equivalent to the reference's global-max subtraction.
// ---------------------------------------------------------------------------
__global__ void __launch_bounds__(256) softmax_kernel(float* __restrict__ s)
{
    const size_t base = ((size_t)blockIdx.y * NTOK + blockIdx.x) * NTOK;
    float4* p = reinterpret_cast<float4*>(s + base);
    const int tid = threadIdx.x;

    float4 v = p[tid];
    float m = fmaxf(fmaxf(v.x, v.y), fmaxf(v.z, v.w));

    __shared__ float red[256];
    red[tid] = m;
    __syncthreads();
    for (int w = 128; w > 0; w >>= 1) {
        if (tid < w) red[tid] = fmaxf(red[tid], red[tid + w]);
        __syncthreads();
    }
    m = red[0];
    __syncthreads();

    v.x = __expf(v.x - m); v.y = __expf(v.y - m);
    v.z = __expf(v.z - m); v.w = __expf(v.w - m);
    red[tid] = v.x + v.y + v.z + v.w;
    __syncthreads();
    for (int w = 128; w > 0; w >>= 1) {
        if (tid < w) red[tid] += red[tid + w];
        __syncthreads();
    }
    const float inv = 1.f / red[0];
    v.x *= inv; v.y *= inv; v.z *= inv; v.w *= inv;
    p[tid] = v;
}

// ---------------------------------------------------------------------------
extern "C" void kernel_launch(void* const* d_in, const int* in_sizes, int n_in,
                              void* d_out, int out_size)
{
    (void)in_sizes; (void)n_in; (void)out_size;
    const float* x     = (const float*)d_in[0];
    const float* gamma = (const float*)d_in[1];
    const float* beta  = (const float*)d_in[2];
    const float* wq    = (const float*)d_in[3];
    const float* bq    = (const float*)d_in[4];
    const float* wk    = (const float*)d_in[5];
    const float* bk    = (const float*)d_in[6];
    const float* wv    = (const float*)d_in[7];
    const float* bv    = (const float*)d_in[8];
    const float* wp    = (const float*)d_in[9];
    const float* bp    = (const float*)d_in[10];
    float* out = (float*)d_out;

    void *p_hn, *p_q, *p_k, *p_v, *p_s, *p_o;
    cudaGetSymbolAddress(&p_hn, g_hn);
    cudaGetSymbolAddress(&p_q,  g_q);
    cudaGetSymbolAddress(&p_k,  g_k);
    cudaGetSymbolAddress(&p_v,  g_v);
    cudaGetSymbolAddress(&p_s,  g_s);
    cudaGetSymbolAddress(&p_o,  g_o);
    float* hn = (float*)p_hn;
    float* q  = (float*)p_q;
    float* k  = (float*)p_k;
    float* v  = (float*)p_v;
    float* s  = (float*)p_s;
    float* o  = (float*)p_o;

    const size_t sBC = (size_t)CCH * NTOK;   // per-batch stride of (c,n) tensors
    const size_t sS  = (size_t)NTOK * NTOK;  // per-batch stride of scores

    // 1) GroupNorm
    gn_kernel<<<dim3(NGRP, BATCH), 256>>>(x, gamma, beta, hn);

    // 2) Q/K/V = W (512x512) @ hn (512x1024) + bias, batched over b
    dim3 gQKV(NTOK / 64, CCH / 64, BATCH);
    gemm_kernel<0, 0, true, false><<<gQKV, 256>>>(wq, hn, bq, nullptr, q,
        CCH, NTOK, CCH, 0, sBC, sBC, 0, 1.f);
    gemm_kernel<0, 0, true, false><<<gQKV, 256>>>(wk, hn, bk, nullptr, k,
        CCH, NTOK, CCH, 0, sBC, sBC, 0, 1.f);
    gemm_kernel<0, 0, true, false><<<gQKV, 256>>>(wv, hn, bv, nullptr, v,
        CCH, NTOK, CCH, 0, sBC, sBC, 0, 1.f);

    // 3) scores s[n][m] = (1/sqrt(512)) * sum_c q[c][n] * k[c][m]  (TN)
    dim3 gS(NTOK / 64, NTOK / 64, BATCH);
    gemm_kernel<1, 0, false, false><<<gS, 256>>>(q, k, nullptr, nullptr, s,
        NTOK, NTOK, CCH, sBC, sBC, sS, 0, 0.044194173824159216f);

    // 4) softmax over m
    softmax_kernel<<<dim3(NTOK, BATCH), 256>>>(s);

    // 5) o[c][n] = sum_m v[c][m] * attn[n][m]  (NT)
    dim3 gAV(NTOK / 64, CCH / 64, BATCH);
    gemm_kernel<0, 1, false, false><<<gAV, 256>>>(v, s, nullptr, nullptr, o,
        CCH, NTOK, NTOK, sBC, sS, sBC, 0, 1.f);

    // 6) out = x + wp @ o + bp
    gemm_kernel<0, 0, true, true><<<gQKV, 256>>>(wp, o, bp, x, out,
        CCH, NTOK, CCH, 0, sBC, sBC, sBC, 1.f);
}

// round 3
// speedup vs baseline: 2.4696x; 2.4696x over previous
#include <cuda_runtime.h>
#include <cstdint>
#include <cstddef>

// ---------------------------------------------------------------------------
// AttnBlock via mma.sync tf32 (arch-portable tensor path; tcgen05 not
// assemblable under this build's ptxas target).
// b=32, c=512, n=1024, groups=16
// ---------------------------------------------------------------------------

#define BATCH 32
#define CCH   512
#define NTOK  1024
#define NGRP  16
#define CPG   (CCH / NGRP)
#define GSIZE (CPG * NTOK)

__device__ float g_hn[(size_t)BATCH * CCH * NTOK];
__device__ float g_q [(size_t)BATCH * CCH * NTOK];
__device__ float g_k [(size_t)BATCH * CCH * NTOK];
__device__ float g_v [(size_t)BATCH * CCH * NTOK];
__device__ float g_o [(size_t)BATCH * CCH * NTOK];
__device__ float g_s [(size_t)BATCH * NTOK * NTOK];

__device__ __forceinline__ uint32_t f2tf32(float f) {
    uint32_t r;
    asm("cvt.rna.tf32.f32 %0, %1;" : "=r"(r) : "f"(f));
    return r;
}

// ---------------------------------------------------------------------------
// Smem operand layout: [row 0..127][k 0..31], pitch 36 words,
// granule swizzle: 16B-granule g (=k/4) stored at g ^ ((row>>3)&7).
// Fragment LDS loads are bank-conflict-free under this layout.
// ---------------------------------------------------------------------------
#define PITCH 36
#define OPWORDS (128 * PITCH)          // 4608 words per operand buffer

__device__ __forceinline__ uint32_t sw_off(int row, int k) {
    return (uint32_t)(row * PITCH + ((((k >> 2) ^ ((row >> 3) & 7)) << 2) | (k & 3)));
}

// gmem -> regs (4 x float4 per thread)
// TRANS=0: src row-major [row][k], ld = row length
// TRANS=1: src K-major   [k][row], ld = row length
template<int TRANS>
__device__ __forceinline__ void g2r(float4* st, const float* __restrict__ src,
                                    int ld, int row0, int k0, int t) {
    #pragma unroll
    for (int j = 0; j < 4; j++) {
        const int i = t + 256 * j;
        if (TRANS == 0) {
            const int r = i >> 3, f4 = i & 7;
            st[j] = *reinterpret_cast<const float4*>(
                &src[(size_t)(row0 + r) * ld + k0 + f4 * 4]);
        } else {
            const int k = i >> 5, rq = i & 31;
            st[j] = *reinterpret_cast<const float4*>(
                &src[(size_t)(k0 + k) * ld + row0 + rq * 4]);
        }
    }
}

// regs -> smem with tf32 convert + swizzle
template<int TRANS>
__device__ __forceinline__ void r2s(float* buf, const float4* st, int t) {
    uint32_t* bu = reinterpret_cast<uint32_t*>(buf);
    #pragma unroll
    for (int j = 0; j < 4; j++) {
        const int i = t + 256 * j;
        if (TRANS == 0) {
            const int r = i >> 3, f4 = i & 7;
            const uint32_t off = (uint32_t)(r * PITCH + ((f4 ^ ((r >> 3) & 7)) << 2));
            uint4 q;
            q.x = f2tf32(st[j].x); q.y = f2tf32(st[j].y);
            q.z = f2tf32(st[j].z); q.w = f2tf32(st[j].w);
            *reinterpret_cast<uint4*>(&bu[off]) = q;
        } else {
            const int k = i >> 5, rq = i & 31;
            const float v[4] = { st[j].x, st[j].y, st[j].z, st[j].w };
            #pragma unroll
            for (int e = 0; e < 4; e++)
                bu[sw_off(rq * 4 + e, k)] = f2tf32(v[e]);
        }
    }
}

// One 32-k chunk of warp-level mma over the 128x128 tile.
__device__ __forceinline__ void compute_chunk(
    const uint32_t* __restrict__ bA, const uint32_t* __restrict__ bB,
    float acc[4][4][4], int wm, int wn, int grp, int tig)
{
    #pragma unroll
    for (int ks = 0; ks < 4; ks++) {
        uint32_t b[4][2];
        #pragma unroll
        for (int nf = 0; nf < 4; nf++) {
            const int n = wn * 32 + nf * 8 + grp;
            const int s3 = (n >> 3) & 7;
            #pragma unroll
            for (int r = 0; r < 2; r++) {
                const int g = 2 * ks + r;
                b[nf][r] = bB[n * PITCH + ((((g ^ s3)) << 2) | tig)];
            }
        }
        uint32_t a[4][4];
        #pragma unroll
        for (int mf = 0; mf < 4; mf++) {
            #pragma unroll
            for (int rr = 0; rr < 4; rr++) {
                const int row = wm * 64 + mf * 16 + (rr & 1) * 8 + grp;
                const int s3 = (row >> 3) & 7;
                const int g = 2 * ks + (rr >> 1);
                a[mf][rr] = bA[row * PITCH + ((((g ^ s3)) << 2) | tig)];
            }
        }
        #pragma unroll
        for (int mf = 0; mf < 4; mf++)
            #pragma unroll
            for (int nf = 0; nf < 4; nf++)
                asm volatile(
                    "mma.sync.aligned.m16n8k8.row.col.f32.tf32.tf32.f32 "
                    "{%0,%1,%2,%3}, {%4,%5,%6,%7}, {%8,%9}, {%0,%1,%2,%3};"
                    : "+f"(acc[mf][nf][0]), "+f"(acc[mf][nf][1]),
                      "+f"(acc[mf][nf][2]), "+f"(acc[mf][nf][3])
                    : "r"(a[mf][0]), "r"(a[mf][1]), "r"(a[mf][2]), "r"(a[mf][3]),
                      "r"(b[nf][0]), "r"(b[nf][1]));
    }
}

// ---------------------------------------------------------------------------
// tf32 GEMM: C[m][n] = scale * sum_k A'[m][k]*B'[n][k] (+bias[m]) (+resid)
// 128x128x32 tile, 256 threads, double-buffered smem, register-staged LDG.
// ---------------------------------------------------------------------------
#define GEMM_SMEM_BYTES (4 * OPWORDS * 4)   // A0,B0,A1,B1 = 73728 bytes

template<int ATRANS, int BTRANS, bool BIAS, bool RESID>
__global__ void __launch_bounds__(256) mma_gemm(
    const float* __restrict__ A, const float* __restrict__ B,
    const float* __restrict__ bias, const float* __restrict__ resid,
    float* __restrict__ C, int M, int N, int K, int ldA, int ldB,
    size_t sA, size_t sB, size_t sC, size_t sR, float scale)
{
    extern __shared__ float sm[];
    float* smA0 = sm;
    float* smB0 = sm + OPWORDS;
    float* smA1 = sm + 2 * OPWORDS;
    float* smB1 = sm + 3 * OPWORDS;

    const int z = blockIdx.z;
    A += (size_t)z * sA;
    B += (size_t)z * sB;
    C += (size_t)z * sC;
    const float* R = RESID ? (resid + (size_t)z * sR) : nullptr;

    const int n0 = blockIdx.x * 128, m0 = blockIdx.y * 128;
    const int t = threadIdx.x;
    const int wid = t >> 5, lane = t & 31;
    const int wm = wid & 1, wn = wid >> 1;      // warp grid 2(M) x 4(N)
    const int grp = lane >> 2, tig = lane & 3;

    float acc[4][4][4] = {};
    float4 stA[4], stB[4];

    g2r<ATRANS>(stA, A, ldA, m0, 0, t);
    g2r<BTRANS>(stB, B, ldB, n0, 0, t);
    r2s<ATRANS>(smA0, stA, t);
    r2s<BTRANS>(smB0, stB, t);
    __syncthreads();

    const int NK = K >> 5;
    for (int kc = 0; kc < NK; kc++) {
        const float* cA = (kc & 1) ? smA1 : smA0;
        const float* cB = (kc & 1) ? smB1 : smB0;
        if (kc + 1 < NK) {
            g2r<ATRANS>(stA, A, ldA, m0, (kc + 1) * 32, t);
            g2r<BTRANS>(stB, B, ldB, n0, (kc + 1) * 32, t);
        }
        compute_chunk(reinterpret_cast<const uint32_t*>(cA),
                      reinterpret_cast<const uint32_t*>(cB),
                      acc, wm, wn, grp, tig);
        if (kc + 1 < NK) {
            float* nA = (kc & 1) ? smA0 : smA1;
            float* nB = (kc & 1) ? smB0 : smB1;
            r2s<ATRANS>(nA, stA, t);
            r2s<BTRANS>(nB, stB, t);
        }
        __syncthreads();
    }

    // epilogue: STG.64 per c-pair, fused scale/bias/residual
    #pragma unroll
    for (int mf = 0; mf < 4; mf++) {
        const int r0 = m0 + wm * 64 + mf * 16 + grp;
        const float ba0 = BIAS ? bias[r0] : 0.f;
        const float ba1 = BIAS ? bias[r0 + 8] : 0.f;
        #pragma unroll
        for (int nf = 0; nf < 4; nf++) {
            const int cc = n0 + wn * 32 + nf * 8 + 2 * tig;
            float2 v0, v1;
            v0.x = acc[mf][nf][0] * scale + ba0;
            v0.y = acc[mf][nf][1] * scale + ba0;
            v1.x = acc[mf][nf][2] * scale + ba1;
            v1.y = acc[mf][nf][3] * scale + ba1;
            if (RESID) {
                const float2 q0 = *reinterpret_cast<const float2*>(&R[(size_t)r0 * N + cc]);
                const float2 q1 = *reinterpret_cast<const float2*>(&R[(size_t)(r0 + 8) * N + cc]);
                v0.x += q0.x; v0.y += q0.y;
                v1.x += q1.x; v1.y += q1.y;
            }
            *reinterpret_cast<float2*>(&C[(size_t)r0 * N + cc]) = v0;
            *reinterpret_cast<float2*>(&C[(size_t)(r0 + 8) * N + cc]) = v1;
        }
    }
}

// ---------------------------------------------------------------------------
// GroupNorm
// ---------------------------------------------------------------------------
__global__ void __launch_bounds__(256) gn_kernel(
    const float* __restrict__ x, const float* __restrict__ gamma,
    const float* __restrict__ beta, float* __restrict__ hn)
{
    const int g = blockIdx.x, b = blockIdx.y;
    const size_t base = ((size_t)b * CCH + (size_t)g * CPG) * NTOK;
    const float4* xp = reinterpret_cast<const float4*>(x + base);
    float4*       hp = reinterpret_cast<float4*>(hn + base);
    const int tid = threadIdx.x;

    float s = 0.f, ss = 0.f;
    for (int i = tid; i < GSIZE / 4; i += 256) {
        float4 v = xp[i];
        s  += v.x + v.y + v.z + v.w;
        ss += v.x * v.x + v.y * v.y + v.z * v.z + v.w * v.w;
    }
    __shared__ float rs[256], rss[256];
    rs[tid] = s; rss[tid] = ss;
    __syncthreads();
    for (int w = 128; w > 0; w >>= 1) {
        if (tid < w) { rs[tid] += rs[tid + w]; rss[tid] += rss[tid + w]; }
        __syncthreads();
    }
    const float mean = rs[0] * (1.f / GSIZE);
    const float var  = rss[0] * (1.f / GSIZE) - mean * mean;
    const float rstd = rsqrtf(var + 1e-6f);

    for (int i = tid; i < GSIZE / 4; i += 256) {
        const int c = g * CPG + (i >> 8);
        const float ga = gamma[c] * rstd;
        const float be = beta[c] - mean * ga;
        float4 v = xp[i];
        v.x = v.x * ga + be; v.y = v.y * ga + be;
        v.z = v.z * ga + be; v.w = v.w * ga + be;
        hp[i] = v;
    }
}

// ---------------------------------------------------------------------------
// Row softmax (per-row max == reference's global shift, by invariance)
// ---------------------------------------------------------------------------
__global__ void __launch_bounds__(256) softmax_kernel(float* __restrict__ s)
{
    const size_t base = ((size_t)blockIdx.y * NTOK + blockIdx.x) * NTOK;
    float4* p = reinterpret_cast<float4*>(s + base);
    const int tid = threadIdx.x;

    float4 v = p[tid];
    float m = fmaxf(fmaxf(v.x, v.y), fmaxf(v.z, v.w));

    __shared__ float red[256];
    red[tid] = m;
    __syncthreads();
    for (int w = 128; w > 0; w >>= 1) {
        if (tid < w) red[tid] = fmaxf(red[tid], red[tid + w]);
        __syncthreads();
    }
    m = red[0];
    __syncthreads();

    v.x = __expf(v.x - m); v.y = __expf(v.y - m);
    v.z = __expf(v.z - m); v.w = __expf(v.w - m);
    red[tid] = v.x + v.y + v.z + v.w;
    __syncthreads();
    for (int w = 128; w > 0; w >>= 1) {
        if (tid < w) red[tid] += red[tid + w];
        __syncthreads();
    }
    const float inv = 1.f / red[0];
    v.x *= inv; v.y *= inv; v.z *= inv; v.w *= inv;
    p[tid] = v;
}

// ---------------------------------------------------------------------------
extern "C" void kernel_launch(void* const* d_in, const int* in_sizes, int n_in,
                              void* d_out, int out_size)
{
    (void)in_sizes; (void)n_in; (void)out_size;
    const float* x     = (const float*)d_in[0];
    const float* gamma = (const float*)d_in[1];
    const float* beta  = (const float*)d_in[2];
    const float* wq    = (const float*)d_in[3];
    const float* bq    = (const float*)d_in[4];
    const float* wk    = (const float*)d_in[5];
    const float* bk    = (const float*)d_in[6];
    const float* wv    = (const float*)d_in[7];
    const float* bv    = (const float*)d_in[8];
    const float* wp    = (const float*)d_in[9];
    const float* bp    = (const float*)d_in[10];
    float* out = (float*)d_out;

    void *p_hn, *p_q, *p_k, *p_v, *p_s, *p_o;
    cudaGetSymbolAddress(&p_hn, g_hn);
    cudaGetSymbolAddress(&p_q,  g_q);
    cudaGetSymbolAddress(&p_k,  g_k);
    cudaGetSymbolAddress(&p_v,  g_v);
    cudaGetSymbolAddress(&p_s,  g_s);
    cudaGetSymbolAddress(&p_o,  g_o);
    float* hn = (float*)p_hn;
    float* q  = (float*)p_q;
    float* k  = (float*)p_k;
    float* v  = (float*)p_v;
    float* s  = (float*)p_s;
    float* o  = (float*)p_o;

    const size_t sBC = (size_t)CCH * NTOK;
    const size_t sS  = (size_t)NTOK * NTOK;

    cudaFuncSetAttribute(mma_gemm<0, 1, true,  false>,
                         cudaFuncAttributeMaxDynamicSharedMemorySize, GEMM_SMEM_BYTES);
    cudaFuncSetAttribute(mma_gemm<1, 1, false, false>,
                         cudaFuncAttributeMaxDynamicSharedMemorySize, GEMM_SMEM_BYTES);
    cudaFuncSetAttribute(mma_gemm<0, 0, false, false>,
                         cudaFuncAttributeMaxDynamicSharedMemorySize, GEMM_SMEM_BYTES);
    cudaFuncSetAttribute(mma_gemm<0, 1, true,  true>,
                         cudaFuncAttributeMaxDynamicSharedMemorySize, GEMM_SMEM_BYTES);

    // 1) GroupNorm
    gn_kernel<<<dim3(NGRP, BATCH), 256>>>(x, gamma, beta, hn);

    // 2) Q/K/V: C[o][n] = sum_c W[o][c]*hn[c][n]; A row-major, B K-major
    dim3 gQKV(NTOK / 128, CCH / 128, BATCH);
    mma_gemm<0, 1, true, false><<<gQKV, 256, GEMM_SMEM_BYTES>>>(
        wq, hn, bq, nullptr, q, CCH, NTOK, CCH, CCH, NTOK, 0, sBC, sBC, 0, 1.f);
    mma_gemm<0, 1, true, false><<<gQKV, 256, GEMM_SMEM_BYTES>>>(
        wk, hn, bk, nullptr, k, CCH, NTOK, CCH, CCH, NTOK, 0, sBC, sBC, 0, 1.f);
    mma_gemm<0, 1, true, false><<<gQKV, 256, GEMM_SMEM_BYTES>>>(
        wv, hn, bv, nullptr, v, CCH, NTOK, CCH, CCH, NTOK, 0, sBC, sBC, 0, 1.f);

    // 3) scores s[n][m] = scale * sum_c q[c][n]*k[c][m]; both K-major
    dim3 gS(NTOK / 128, NTOK / 128, BATCH);
    mma_gemm<1, 1, false, false><<<gS, 256, GEMM_SMEM_BYTES>>>(
        q, k, nullptr, nullptr, s, NTOK, NTOK, CCH, NTOK, NTOK,
        sBC, sBC, sS, 0, 0.04419417382415922f);

    // 4) softmax over m
    softmax_kernel<<<dim3(NTOK, BATCH), 256>>>(s);

    // 5) o[c][n] = sum_m v[c][m]*attn[n][m]; both row-major
    dim3 gAV(NTOK / 128, CCH / 128, BATCH);
    mma_gemm<0, 0, false, false><<<gAV, 256, GEMM_SMEM_BYTES>>>(
        v, s, nullptr, nullptr, o, CCH, NTOK, NTOK, NTOK, NTOK, sBC, sS, sBC, 0, 1.f);

    // 6) out = x + wp @ o + bp
    mma_gemm<0, 1, true, true><<<gQKV, 256, GEMM_SMEM_BYTES>>>(
        wp, o, bp, x, out, CCH, NTOK, CCH, CCH, NTOK, 0, sBC, sBC, sBC, 1.f);
}

// round 6
// speedup vs baseline: 3.7344x; 1.5122x over previous
#include <cuda_runtime.h>
#include <cuda_fp16.h>
#include <cstdint>
#include <cstddef>

// ===========================================================================
// AttnBlock: GroupNorm -> QKV -> softmax attention -> proj + residual
// fp16 tensor-core path (mma.sync m16n8k16, f32 accumulate), fp16 scratch.
// b=32, c=512, n=h*w=1024, groups=16
// ===========================================================================

#define BATCH 32
#define CCH   512
#define NTOK  1024
#define NGRP  16
#define CPG   (CCH / NGRP)
#define GSIZE (CPG * NTOK)

// Device-global scratch (allocation-free per harness rules)
__device__ __half sc_hn[(size_t)BATCH * CCH * NTOK];
__device__ __half sc_q [(size_t)BATCH * CCH * NTOK];
__device__ __half sc_k [(size_t)BATCH * CCH * NTOK];
__device__ __half sc_v [(size_t)BATCH * CCH * NTOK];
__device__ __half sc_o [(size_t)BATCH * CCH * NTOK];
__device__ __half sc_at[(size_t)BATCH * NTOK * NTOK];
__device__ float  sc_s [(size_t)BATCH * NTOK * NTOK];
__device__ __half sc_w [4 * CCH * CCH];

// ---------------------------------------------------------------------------
// Smem operand layout: [row 0..127][kw 0..15] (kw = packed half-pair),
// row pitch 20 words. Bank math: word = row*20 + kw. Within a fragment load,
// lanes (grp = lane>>2, tig = lane&3) hit word grp*20 + tig (+const), and
// {grp*20 + tig mod 32} is a permutation of 0..31 -> conflict-free. All
// fragment-offset constants (mf*320, nf*160, 8 rows = 160, ks*8, +4) keep
// that property.
// ---------------------------------------------------------------------------
#define PITCHW 20
#define OPW    (128 * PITCHW)   // words per operand buffer (2560)

struct Stage { uint32_t w[8]; };

// gmem(half) -> registers. TR=0: src row-major [row][k]. TR=1: src [k][row].
template<int TR>
__device__ __forceinline__ Stage ldg_tile(const __half* __restrict__ src,
                                          int ld, int row0, int k0, int t) {
    Stage st;
    if (TR == 0) {
        const int r = t >> 1, h = t & 1;
        const __half* p = src + (size_t)(row0 + r) * ld + k0 + 16 * h;
        const uint4 u0 = *reinterpret_cast<const uint4*>(p);
        const uint4 u1 = *reinterpret_cast<const uint4*>(p + 8);
        st.w[0] = u0.x; st.w[1] = u0.y; st.w[2] = u0.z; st.w[3] = u0.w;
        st.w[4] = u1.x; st.w[5] = u1.y; st.w[6] = u1.z; st.w[7] = u1.w;
    } else {
        const int kp = t & 15, nb = t >> 4;
        const __half* p = src + (size_t)(k0 + 2 * kp) * ld + row0 + nb * 8;
        const uint4 u0 = *reinterpret_cast<const uint4*>(p);
        const uint4 u1 = *reinterpret_cast<const uint4*>(p + ld);
        st.w[0] = u0.x; st.w[1] = u0.y; st.w[2] = u0.z; st.w[3] = u0.w;
        st.w[4] = u1.x; st.w[5] = u1.y; st.w[6] = u1.z; st.w[7] = u1.w;
    }
    return st;
}

// registers -> smem (transpose-pack for TR=1 via byte_perm)
template<int TR>
__device__ __forceinline__ void sts_tile(uint32_t* __restrict__ buf,
                                         const Stage& st, int t) {
    if (TR == 0) {
        const int r = t >> 1, h = t & 1;
        uint32_t* d = buf + r * PITCHW + 8 * h;
        #pragma unroll
        for (int e = 0; e < 4; e++)
            *reinterpret_cast<uint2*>(d + 2 * e) = make_uint2(st.w[2 * e], st.w[2 * e + 1]);
    } else {
        const int kp = t & 15, nb = t >> 4;
        #pragma unroll
        for (int e2 = 0; e2 < 4; e2++) {
            const uint32_t lo = __byte_perm(st.w[e2], st.w[4 + e2], 0x5410);
            const uint32_t hi = __byte_perm(st.w[e2], st.w[4 + e2], 0x7632);
            buf[(nb * 8 + 2 * e2 + 0) * PITCHW + kp] = lo;
            buf[(nb * 8 + 2 * e2 + 1) * PITCHW + kp] = hi;
        }
    }
}

__device__ __forceinline__ void mma16816(float d[4], const uint32_t a[4],
                                         const uint32_t b[2]) {
    asm volatile(
        "mma.sync.aligned.m16n8k16.row.col.f32.f16.f16.f32 "
        "{%0,%1,%2,%3}, {%4,%5,%6,%7}, {%8,%9}, {%0,%1,%2,%3};"
        : "+f"(d[0]), "+f"(d[1]), "+f"(d[2]), "+f"(d[3])
        : "r"(a[0]), "r"(a[1]), "r"(a[2]), "r"(a[3]), "r"(b[0]), "r"(b[1]));
}

// ---------------------------------------------------------------------------
// fp16 GEMM: C[m][n] = scale * sum_k A'[m][k]*B'[n][k] (+bias[m]) (+resid)
// 128x128x32 CTA tile, 8 warps (2M x 4N), warp tile 64x32, double-buffered.
// ---------------------------------------------------------------------------
template<int AT, int BT, bool BIAS, bool RESID, bool HOUT>
__global__ void __launch_bounds__(256, 2) hgemm(
    const __half* __restrict__ A, const __half* __restrict__ B,
    const float* __restrict__ bias, const float* __restrict__ resid,
    void* __restrict__ Cv, int N, int K, int ldA, int ldB,
    size_t sA, size_t sB, size_t sC, size_t sR, float scale)
{
    __shared__ uint32_t smbuf[4 * OPW];    // A0 B0 A1 B1 : 40 KiB

    const int z = blockIdx.z;
    A += (size_t)z * sA;
    B += (size_t)z * sB;
    const float* R = RESID ? (resid + (size_t)z * sR) : nullptr;

    const int n0 = blockIdx.x * 128, m0 = blockIdx.y * 128;
    const int t = threadIdx.x;
    const int wid = t >> 5, lane = t & 31;
    const int wm = wid & 1, wn = wid >> 1;
    const int grp = lane >> 2, tig = lane & 3;

    float acc[4][4][4] = {};

    Stage stA = ldg_tile<AT>(A, ldA, m0, 0, t);
    Stage stB = ldg_tile<BT>(B, ldB, n0, 0, t);
    sts_tile<AT>(smbuf, stA, t);
    sts_tile<BT>(smbuf + OPW, stB, t);
    __syncthreads();

    const uint32_t baseA = (wm * 64 + grp) * PITCHW + tig;
    const uint32_t baseB = (wn * 32 + grp) * PITCHW + tig;

    const int NK = K >> 5;
    for (int kc = 0; kc < NK; kc++) {
        const uint32_t* bufA = smbuf + ((kc & 1) ? 2 * OPW : 0);
        const uint32_t* bufB = bufA + OPW;
        if (kc + 1 < NK) {
            stA = ldg_tile<AT>(A, ldA, m0, (kc + 1) * 32, t);
            stB = ldg_tile<BT>(B, ldB, n0, (kc + 1) * 32, t);
        }
        #pragma unroll
        for (int ks = 0; ks < 2; ks++) {
            uint32_t af[4][4], bf[4][2];
            #pragma unroll
            for (int mf = 0; mf < 4; mf++) {
                const uint32_t ba = baseA + mf * (16 * PITCHW) + ks * 8;
                af[mf][0] = bufA[ba];
                af[mf][1] = bufA[ba + 8 * PITCHW];
                af[mf][2] = bufA[ba + 4];
                af[mf][3] = bufA[ba + 8 * PITCHW + 4];
            }
            #pragma unroll
            for (int nf = 0; nf < 4; nf++) {
                const uint32_t bb = baseB + nf * (8 * PITCHW) + ks * 8;
                bf[nf][0] = bufB[bb];
                bf[nf][1] = bufB[bb + 4];
            }
            #pragma unroll
            for (int mf = 0; mf < 4; mf++)
                #pragma unroll
                for (int nf = 0; nf < 4; nf++)
                    mma16816(acc[mf][nf], af[mf], bf[nf]);
        }
        if (kc + 1 < NK) {
            uint32_t* nA = smbuf + ((kc & 1) ? 0 : 2 * OPW);
            sts_tile<AT>(nA, stA, t);
            sts_tile<BT>(nA + OPW, stB, t);
        }
        __syncthreads();
    }

    // ---- epilogue: fused scale / bias / residual, vectorized stores ----
    #pragma unroll
    for (int mf = 0; mf < 4; mf++) {
        const int r0 = m0 + wm * 64 + mf * 16 + grp;
        const float ba0 = BIAS ? bias[r0] : 0.f;
        const float ba1 = BIAS ? bias[r0 + 8] : 0.f;
        #pragma unroll
        for (int nf = 0; nf < 4; nf++) {
            const int cc = n0 + wn * 32 + nf * 8 + 2 * tig;
            float2 v0, v1;
            v0.x = acc[mf][nf][0] * scale + ba0;
            v0.y = acc[mf][nf][1] * scale + ba0;
            v1.x = acc[mf][nf][2] * scale + ba1;
            v1.y = acc[mf][nf][3] * scale + ba1;
            if (RESID) {
                const float2 q0 = *reinterpret_cast<const float2*>(&R[(size_t)r0 * N + cc]);
                const float2 q1 = *reinterpret_cast<const float2*>(&R[(size_t)(r0 + 8) * N + cc]);
                v0.x += q0.x; v0.y += q0.y;
                v1.x += q1.x; v1.y += q1.y;
            }
            if (HOUT) {
                __half* C = (__half*)Cv + (size_t)z * sC;
                *reinterpret_cast<__half2*>(&C[(size_t)r0 * N + cc]) =
                    __floats2half2_rn(v0.x, v0.y);
                *reinterpret_cast<__half2*>(&C[(size_t)(r0 + 8) * N + cc]) =
                    __floats2half2_rn(v1.x, v1.y);
            } else {
                float* C = (float*)Cv + (size_t)z * sC;
                *reinterpret_cast<float2*>(&C[(size_t)r0 * N + cc]) = v0;
                *reinterpret_cast<float2*>(&C[(size_t)(r0 + 8) * N + cc]) = v1;
            }
        }
    }
}

// ---------------------------------------------------------------------------
// fp32 -> fp16 weight conversion (one float4 per thread)
// ---------------------------------------------------------------------------
__global__ void __launch_bounds__(256) cvt_w_kernel(const float* __restrict__ src,
                                                    __half* __restrict__ dst) {
    const int i = blockIdx.x * 256 + threadIdx.x;
    const float4 v = reinterpret_cast<const float4*>(src)[i];
    __half2* d = reinterpret_cast<__half2*>(dst) + i * 2;
    d[0] = __floats2half2_rn(v.x, v.y);
    d[1] = __floats2half2_rn(v.z, v.w);
}

// ---------------------------------------------------------------------------
// GroupNorm -> fp16
// ---------------------------------------------------------------------------
__global__ void __launch_bounds__(256) groupnorm_kernel(
    const float* __restrict__ x, const float* __restrict__ gamma,
    const float* __restrict__ beta, __half* __restrict__ hn)
{
    const int g = blockIdx.x, b = blockIdx.y;
    const size_t base = ((size_t)b * CCH + (size_t)g * CPG) * NTOK;
    const float4* xp = reinterpret_cast<const float4*>(x + base);
    __half2*      hp = reinterpret_cast<__half2*>(hn + base);
    const int tid = threadIdx.x;

    float s = 0.f, ss = 0.f;
    for (int i = tid; i < GSIZE / 4; i += 256) {
        const float4 v = xp[i];
        s  += v.x + v.y + v.z + v.w;
        ss += v.x * v.x + v.y * v.y + v.z * v.z + v.w * v.w;
    }
    __shared__ float rs[256], rss[256];
    rs[tid] = s; rss[tid] = ss;
    __syncthreads();
    for (int w = 128; w > 0; w >>= 1) {
        if (tid < w) { rs[tid] += rs[tid + w]; rss[tid] += rss[tid + w]; }
        __syncthreads();
    }
    const float mean = rs[0] * (1.f / GSIZE);
    const float var  = rss[0] * (1.f / GSIZE) - mean * mean;
    const float rstd = rsqrtf(var + 1e-6f);

    for (int i = tid; i < GSIZE / 4; i += 256) {
        const int c = g * CPG + (i >> 8);
        const float ga = gamma[c] * rstd;
        const float be = beta[c] - mean * ga;
        const float4 v = xp[i];
        hp[i * 2 + 0] = __floats2half2_rn(v.x * ga + be, v.y * ga + be);
        hp[i * 2 + 1] = __floats2half2_rn(v.z * ga + be, v.w * ga + be);
    }
}

// ---------------------------------------------------------------------------
// Row softmax: fp32 scores -> fp16 probabilities.
// Per-row max == reference's global-max shift (softmax shift invariance).
// ---------------------------------------------------------------------------
__global__ void __launch_bounds__(256) softmax_kernel(
    const float* __restrict__ s, __half* __restrict__ attn)
{
    const size_t base = ((size_t)blockIdx.y * NTOK + blockIdx.x) * NTOK;
    const float4* p = reinterpret_cast<const float4*>(s + base);
    __half2*      o = reinterpret_cast<__half2*>(attn + base);
    const int tid = threadIdx.x;

    float4 v = p[tid];
    float m = fmaxf(fmaxf(v.x, v.y), fmaxf(v.z, v.w));

    __shared__ float red[256];
    red[tid] = m;
    __syncthreads();
    for (int w = 128; w > 0; w >>= 1) {
        if (tid < w) red[tid] = fmaxf(red[tid], red[tid + w]);
        __syncthreads();
    }
    m = red[0];
    __syncthreads();

    v.x = __expf(v.x - m); v.y = __expf(v.y - m);
    v.z = __expf(v.z - m); v.w = __expf(v.w - m);
    red[tid] = v.x + v.y + v.z + v.w;
    __syncthreads();
    for (int w = 128; w > 0; w >>= 1) {
        if (tid < w) red[tid] += red[tid + w];
        __syncthreads();
    }
    const float inv = 1.f / red[0];
    o[tid * 2 + 0] = __floats2half2_rn(v.x * inv, v.y * inv);
    o[tid * 2 + 1] = __floats2half2_rn(v.z * inv, v.w * inv);
}

// ---------------------------------------------------------------------------
extern "C" void kernel_launch(void* const* d_in, const int* in_sizes, int n_in,
                              void* d_out, int out_size)
{
    (void)in_sizes; (void)n_in; (void)out_size;
    const float* x     = (const float*)d_in[0];
    const float* gamma = (const float*)d_in[1];
    const float* beta  = (const float*)d_in[2];
    const float* wq    = (const float*)d_in[3];
    const float* bq    = (const float*)d_in[4];
    const float* wk    = (const float*)d_in[5];
    const float* bk    = (const float*)d_in[6];
    const float* wv    = (const float*)d_in[7];
    const float* bv    = (const float*)d_in[8];
    const float* wp    = (const float*)d_in[9];
    const float* bp    = (const float*)d_in[10];
    float* out = (float*)d_out;

    void *p0, *p1, *p2, *p3, *p4, *p5, *p6, *p7;
    cudaGetSymbolAddress(&p0, sc_hn);
    cudaGetSymbolAddress(&p1, sc_q);
    cudaGetSymbolAddress(&p2, sc_k);
    cudaGetSymbolAddress(&p3, sc_v);
    cudaGetSymbolAddress(&p4, sc_o);
    cudaGetSymbolAddress(&p5, sc_at);
    cudaGetSymbolAddress(&p6, sc_s);
    cudaGetSymbolAddress(&p7, sc_w);
    __half* hn = (__half*)p0;
    __half* q  = (__half*)p1;
    __half* k  = (__half*)p2;
    __half* v  = (__half*)p3;
    __half* o  = (__half*)p4;
    __half* at = (__half*)p5;
    float*  s  = (float*)p6;
    __half* wh = (__half*)p7;
    __half* whq = wh;
    __half* whk = wh + (size_t)CCH * CCH;
    __half* whv = wh + (size_t)2 * CCH * CCH;
    __half* whp = wh + (size_t)3 * CCH * CCH;

    const size_t sBC = (size_t)CCH * NTOK;
    const size_t sS  = (size_t)NTOK * NTOK;
    const int WBLK = CCH * CCH / 1024;

    cvt_w_kernel<<<WBLK, 256>>>(wq, whq);
    cvt_w_kernel<<<WBLK, 256>>>(wk, whk);
    cvt_w_kernel<<<WBLK, 256>>>(wv, whv);
    cvt_w_kernel<<<WBLK, 256>>>(wp, whp);

    groupnorm_kernel<<<dim3(NGRP, BATCH), 256>>>(x, gamma, beta, hn);

    // Q/K/V: C[oc][n] = sum_c W[oc][c] * hn[c][n]
    dim3 gQKV(NTOK / 128, CCH / 128, BATCH);
    hgemm<0, 1, true, false, true><<<gQKV, 256>>>(
        whq, hn, bq, nullptr, q, NTOK, CCH, CCH, NTOK, 0, sBC, sBC, 0, 1.f);
    hgemm<0, 1, true, false, true><<<gQKV, 256>>>(
        whk, hn, bk, nullptr, k, NTOK, CCH, CCH, NTOK, 0, sBC, sBC, 0, 1.f);
    hgemm<0, 1, true, false, true><<<gQKV, 256>>>(
        whv, hn, bv, nullptr, v, NTOK, CCH, CCH, NTOK, 0, sBC, sBC, 0, 1.f);

    // scores s[n][m] = scale * sum_c q[c][n] * k[c][m]
    dim3 gS(NTOK / 128, NTOK / 128, BATCH);
    hgemm<1, 1, false, false, false><<<gS, 256>>>(
        q, k, nullptr, nullptr, s, NTOK, CCH, NTOK, NTOK,
        sBC, sBC, sS, 0, 0.04419417382415922f);

    softmax_kernel<<<dim3(NTOK, BATCH), 256>>>(s, at);

    // o[c][n] = sum_m v[c][m] * attn[n][m]
    dim3 gAV(NTOK / 128, CCH / 128, BATCH);
    hgemm<0, 0, false, false, true><<<gAV, 256>>>(
        v, at, nullptr, nullptr, o, NTOK, NTOK, NTOK, NTOK, sBC, sS, sBC, 0, 1.f);

    // out = x + wp @ o + bp
    hgemm<0, 1, true, true, false><<<gQKV, 256>>>(
        whp, o, bp, x, out, NTOK, CCH, CCH, NTOK, 0, sBC, sBC, sBC, 1.f);
}

// round 7
// speedup vs baseline: 4.1204x; 1.1034x over previous
#include <cuda_runtime.h>
#include <cuda_fp16.h>
#include <cstdint>
#include <cstddef>

// ===========================================================================
// AttnBlock: GroupNorm -> QKV -> softmax attention -> proj + residual
// fp16 tensor-core path (mma.sync m16n8k16 + ldmatrix), fp16 scratch.
// b=32, c=512, n=h*w=1024, groups=16
// ===========================================================================

#define BATCH 32
#define CCH   512
#define NTOK  1024
#define NGRP  16
#define CPG   (CCH / NGRP)
#define GSIZE (CPG * NTOK)

// Device-global scratch (allocation-free per harness rules)
__device__ __half sc_hn[(size_t)BATCH * CCH * NTOK];
__device__ __half sc_q [(size_t)BATCH * CCH * NTOK];
__device__ __half sc_k [(size_t)BATCH * CCH * NTOK];
__device__ __half sc_v [(size_t)BATCH * CCH * NTOK];
__device__ __half sc_o [(size_t)BATCH * CCH * NTOK];
__device__ __half sc_at[(size_t)BATCH * NTOK * NTOK];
__device__ float  sc_s [(size_t)BATCH * NTOK * NTOK];
__device__ __half sc_w [4 * CCH * CCH];

// ---------------------------------------------------------------------------
// Smem operand layout: [row 0..127][kw 0..15] (kw = packed half-pair),
// row pitch 20 words. ldmatrix-friendly: 8 consecutive rows start at word
// offsets {0,20,8,28,16,4,24,12} mod 32 -> the eight 16B reads of one 8x8
// matrix tile all 32 banks exactly (also true shifted by +4 words).
// ---------------------------------------------------------------------------
#define PITCHW 20
#define OPW    (128 * PITCHW)   // words per operand buffer (2560)

struct Stage { uint32_t w[8]; };

// gmem(half) -> registers. TR=0: src row-major [row][k]. TR=1: src [k][row].
template<int TR>
__device__ __forceinline__ Stage ldg_tile(const __half* __restrict__ src,
                                          int ld, int row0, int k0, int t) {
    Stage st;
    if (TR == 0) {
        const int r = t >> 1, h = t & 1;
        const __half* p = src + (size_t)(row0 + r) * ld + k0 + 16 * h;
        const uint4 u0 = *reinterpret_cast<const uint4*>(p);
        const uint4 u1 = *reinterpret_cast<const uint4*>(p + 8);
        st.w[0] = u0.x; st.w[1] = u0.y; st.w[2] = u0.z; st.w[3] = u0.w;
        st.w[4] = u1.x; st.w[5] = u1.y; st.w[6] = u1.z; st.w[7] = u1.w;
    } else {
        const int kp = t & 15, nb = t >> 4;
        const __half* p = src + (size_t)(k0 + 2 * kp) * ld + row0 + nb * 8;
        const uint4 u0 = *reinterpret_cast<const uint4*>(p);
        const uint4 u1 = *reinterpret_cast<const uint4*>(p + ld);
        st.w[0] = u0.x; st.w[1] = u0.y; st.w[2] = u0.z; st.w[3] = u0.w;
        st.w[4] = u1.x; st.w[5] = u1.y; st.w[6] = u1.z; st.w[7] = u1.w;
    }
    return st;
}

// registers -> smem (transpose-pack for TR=1 via byte_perm)
template<int TR>
__device__ __forceinline__ void sts_tile(uint32_t* __restrict__ buf,
                                         const Stage& st, int t) {
    if (TR == 0) {
        const int r = t >> 1, h = t & 1;
        uint32_t* d = buf + r * PITCHW + 8 * h;
        #pragma unroll
        for (int e = 0; e < 4; e++)
            *reinterpret_cast<uint2*>(d + 2 * e) = make_uint2(st.w[2 * e], st.w[2 * e + 1]);
    } else {
        const int kp = t & 15, nb = t >> 4;
        #pragma unroll
        for (int e2 = 0; e2 < 4; e2++) {
            const uint32_t lo = __byte_perm(st.w[e2], st.w[4 + e2], 0x5410);
            const uint32_t hi = __byte_perm(st.w[e2], st.w[4 + e2], 0x7632);
            buf[(nb * 8 + 2 * e2 + 0) * PITCHW + kp] = lo;
            buf[(nb * 8 + 2 * e2 + 1) * PITCHW + kp] = hi;
        }
    }
}

__device__ __forceinline__ void mma16816(float d[4], const uint32_t a[4],
                                         const uint32_t b[2]) {
    asm volatile(
        "mma.sync.aligned.m16n8k16.row.col.f32.f16.f16.f32 "
        "{%0,%1,%2,%3}, {%4,%5,%6,%7}, {%8,%9}, {%0,%1,%2,%3};"
        : "+f"(d[0]), "+f"(d[1]), "+f"(d[2]), "+f"(d[3])
        : "r"(a[0]), "r"(a[1]), "r"(a[2]), "r"(a[3]), "r"(b[0]), "r"(b[1]));
}

#define LDMX4(r0, r1, r2, r3, addr) \
    asm volatile("ldmatrix.sync.aligned.m8n8.x4.shared.b16 {%0,%1,%2,%3}, [%4];" \
                 : "=r"(r0), "=r"(r1), "=r"(r2), "=r"(r3) : "r"(addr))

// ---------------------------------------------------------------------------
// fp16 GEMM: C[m][n] = scale * sum_k A'[m][k]*B'[n][k] (+bias[m]) (+resid)
// 128x128x32 CTA tile, 8 warps (2M x 4N), warp tile 64x32, double-buffered,
// ldmatrix fragment loads.
// ---------------------------------------------------------------------------
template<int AT, int BT, bool BIAS, bool RESID, bool HOUT>
__global__ void __launch_bounds__(256, 2) hgemm(
    const __half* __restrict__ A, const __half* __restrict__ B,
    const float* __restrict__ bias, const float* __restrict__ resid,
    void* __restrict__ Cv, int N, int K, int ldA, int ldB,
    size_t sA, size_t sB, size_t sC, size_t sR, float scale)
{
    __shared__ __align__(16) uint32_t smbuf[4 * OPW];   // A0 B0 A1 B1 : 40 KiB

    const int z = blockIdx.z;
    A += (size_t)z * sA;
    B += (size_t)z * sB;
    const float* R = RESID ? (resid + (size_t)z * sR) : nullptr;

    const int n0 = blockIdx.x * 128, m0 = blockIdx.y * 128;
    const int t = threadIdx.x;
    const int wid = t >> 5, lane = t & 31;
    const int wm = wid & 1, wn = wid >> 1;
    const int grp = lane >> 2, tig = lane & 3;

    float acc[4][4][4] = {};

    Stage stA = ldg_tile<AT>(A, ldA, m0, 0, t);
    Stage stB = ldg_tile<BT>(B, ldB, n0, 0, t);
    sts_tile<AT>(smbuf, stA, t);
    sts_tile<BT>(smbuf + OPW, stB, t);
    __syncthreads();

    const uint32_t smBase = (uint32_t)__cvta_generic_to_shared(smbuf);
    // ldmatrix per-lane byte offsets within an operand buffer:
    //  A x4 covers m16k16: matrices [m0-7,klo],[m8-15,klo],[m0-7,khi],[m8-15,khi]
    const uint32_t laneA =
        ((uint32_t)(wm * 64 + (lane & 7) + 8 * ((lane >> 3) & 1)) * PITCHW
         + 4u * ((lane >> 4) & 1)) * 4u;
    //  B x4 covers two n8k16 frags: [n0-7,klo],[n0-7,khi],[n8-15,klo],[n8-15,khi]
    const uint32_t laneB =
        ((uint32_t)(wn * 32 + (lane & 7) + 8 * ((lane >> 4) & 1)) * PITCHW
         + 4u * ((lane >> 3) & 1)) * 4u;

    const int NK = K >> 5;
    for (int kc = 0; kc < NK; kc++) {
        const uint32_t aBuf = smBase + ((kc & 1) ? (uint32_t)(2 * OPW * 4) : 0u);
        const uint32_t bBuf = aBuf + (uint32_t)(OPW * 4);
        if (kc + 1 < NK) {
            stA = ldg_tile<AT>(A, ldA, m0, (kc + 1) * 32, t);
            stB = ldg_tile<BT>(B, ldB, n0, (kc + 1) * 32, t);
        }
        #pragma unroll
        for (int ks = 0; ks < 2; ks++) {
            uint32_t af[4][4], bf[4][2];
            #pragma unroll
            for (int mf = 0; mf < 4; mf++)
                LDMX4(af[mf][0], af[mf][1], af[mf][2], af[mf][3],
                      aBuf + laneA + (uint32_t)(mf * 16 * PITCHW * 4 + ks * 32));
            LDMX4(bf[0][0], bf[0][1], bf[1][0], bf[1][1],
                  bBuf + laneB + (uint32_t)(ks * 32));
            LDMX4(bf[2][0], bf[2][1], bf[3][0], bf[3][1],
                  bBuf + laneB + (uint32_t)(16 * PITCHW * 4 + ks * 32));
            #pragma unroll
            for (int mf = 0; mf < 4; mf++)
                #pragma unroll
                for (int nf = 0; nf < 4; nf++)
                    mma16816(acc[mf][nf], af[mf], bf[nf]);
        }
        if (kc + 1 < NK) {
            uint32_t* nA = smbuf + ((kc & 1) ? 0 : 2 * OPW);
            sts_tile<AT>(nA, stA, t);
            sts_tile<BT>(nA + OPW, stB, t);
        }
        __syncthreads();
    }

    // ---- epilogue: fused scale / bias / residual, vectorized stores ----
    #pragma unroll
    for (int mf = 0; mf < 4; mf++) {
        const int r0 = m0 + wm * 64 + mf * 16 + grp;
        const float ba0 = BIAS ? bias[r0] : 0.f;
        const float ba1 = BIAS ? bias[r0 + 8] : 0.f;
        #pragma unroll
        for (int nf = 0; nf < 4; nf++) {
            const int cc = n0 + wn * 32 + nf * 8 + 2 * tig;
            float2 v0, v1;
            v0.x = acc[mf][nf][0] * scale + ba0;
            v0.y = acc[mf][nf][1] * scale + ba0;
            v1.x = acc[mf][nf][2] * scale + ba1;
            v1.y = acc[mf][nf][3] * scale + ba1;
            if (RESID) {
                const float2 q0 = *reinterpret_cast<const float2*>(&R[(size_t)r0 * N + cc]);
                const float2 q1 = *reinterpret_cast<const float2*>(&R[(size_t)(r0 + 8) * N + cc]);
                v0.x += q0.x; v0.y += q0.y;
                v1.x += q1.x; v1.y += q1.y;
            }
            if (HOUT) {
                __half* C = (__half*)Cv + (size_t)z * sC;
                *reinterpret_cast<__half2*>(&C[(size_t)r0 * N + cc]) =
                    __floats2half2_rn(v0.x, v0.y);
                *reinterpret_cast<__half2*>(&C[(size_t)(r0 + 8) * N + cc]) =
                    __floats2half2_rn(v1.x, v1.y);
            } else {
                float* C = (float*)Cv + (size_t)z * sC;
                *reinterpret_cast<float2*>(&C[(size_t)r0 * N + cc]) = v0;
                *reinterpret_cast<float2*>(&C[(size_t)(r0 + 8) * N + cc]) = v1;
            }
        }
    }
}

// ---------------------------------------------------------------------------
// fp32 -> fp16 weight conversion (one float4 per thread)
// ---------------------------------------------------------------------------
__global__ void __launch_bounds__(256) cvt_w_kernel(const float* __restrict__ src,
                                                    __half* __restrict__ dst) {
    const int i = blockIdx.x * 256 + threadIdx.x;
    const float4 v = reinterpret_cast<const float4*>(src)[i];
    __half2* d = reinterpret_cast<__half2*>(dst) + i * 2;
    d[0] = __floats2half2_rn(v.x, v.y);
    d[1] = __floats2half2_rn(v.z, v.w);
}

// ---------------------------------------------------------------------------
// GroupNorm -> fp16
// ---------------------------------------------------------------------------
__global__ void __launch_bounds__(256) groupnorm_kernel(
    const float* __restrict__ x, const float* __restrict__ gamma,
    const float* __restrict__ beta, __half* __restrict__ hn)
{
    const int g = blockIdx.x, b = blockIdx.y;
    const size_t base = ((size_t)b * CCH + (size_t)g * CPG) * NTOK;
    const float4* xp = reinterpret_cast<const float4*>(x + base);
    __half2*      hp = reinterpret_cast<__half2*>(hn + base);
    const int tid = threadIdx.x;

    float s = 0.f, ss = 0.f;
    for (int i = tid; i < GSIZE / 4; i += 256) {
        const float4 v = xp[i];
        s  += v.x + v.y + v.z + v.w;
        ss += v.x * v.x + v.y * v.y + v.z * v.z + v.w * v.w;
    }
    __shared__ float rs[256], rss[256];
    rs[tid] = s; rss[tid] = ss;
    __syncthreads();
    for (int w = 128; w > 0; w >>= 1) {
        if (tid < w) { rs[tid] += rs[tid + w]; rss[tid] += rss[tid + w]; }
        __syncthreads();
    }
    const float mean = rs[0] * (1.f / GSIZE);
    const float var  = rss[0] * (1.f / GSIZE) - mean * mean;
    const float rstd = rsqrtf(var + 1e-6f);

    for (int i = tid; i < GSIZE / 4; i += 256) {
        const int c = g * CPG + (i >> 8);
        const float ga = gamma[c] * rstd;
        const float be = beta[c] - mean * ga;
        const float4 v = xp[i];
        hp[i * 2 + 0] = __floats2half2_rn(v.x * ga + be, v.y * ga + be);
        hp[i * 2 + 1] = __floats2half2_rn(v.z * ga + be, v.w * ga + be);
    }
}

// ---------------------------------------------------------------------------
// Row softmax: fp32 scores -> fp16 probabilities.
// Per-row max == reference's global-max shift (softmax shift invariance).
// ---------------------------------------------------------------------------
__global__ void __launch_bounds__(256) softmax_kernel(
    const float* __restrict__ s, __half* __restrict__ attn)
{
    const size_t base = ((size_t)blockIdx.y * NTOK + blockIdx.x) * NTOK;
    const float4* p = reinterpret_cast<const float4*>(s + base);
    __half2*      o = reinterpret_cast<__half2*>(attn + base);
    const int tid = threadIdx.x;

    float4 v = p[tid];
    float m = fmaxf(fmaxf(v.x, v.y), fmaxf(v.z, v.w));

    __shared__ float red[256];
    red[tid] = m;
    __syncthreads();
    for (int w = 128; w > 0; w >>= 1) {
        if (tid < w) red[tid] = fmaxf(red[tid], red[tid + w]);
        __syncthreads();
    }
    m = red[0];
    __syncthreads();

    v.x = __expf(v.x - m); v.y = __expf(v.y - m);
    v.z = __expf(v.z - m); v.w = __expf(v.w - m);
    red[tid] = v.x + v.y + v.z + v.w;
    __syncthreads();
    for (int w = 128; w > 0; w >>= 1) {
        if (tid < w) red[tid] += red[tid + w];
        __syncthreads();
    }
    const float inv = 1.f / red[0];
    o[tid * 2 + 0] = __floats2half2_rn(v.x * inv, v.y * inv);
    o[tid * 2 + 1] = __floats2half2_rn(v.z * inv, v.w * inv);
}

// ---------------------------------------------------------------------------
extern "C" void kernel_launch(void* const* d_in, const int* in_sizes, int n_in,
                              void* d_out, int out_size)
{
    (void)in_sizes; (void)n_in; (void)out_size;
    const float* x     = (const float*)d_in[0];
    const float* gamma = (const float*)d_in[1];
    const float* beta  = (const float*)d_in[2];
    const float* wq    = (const float*)d_in[3];
    const float* bq    = (const float*)d_in[4];
    const float* wk    = (const float*)d_in[5];
    const float* bk    = (const float*)d_in[6];
    const float* wv    = (const float*)d_in[7];
    const float* bv    = (const float*)d_in[8];
    const float* wp    = (const float*)d_in[9];
    const float* bp    = (const float*)d_in[10];
    float* out = (float*)d_out;

    void *p0, *p1, *p2, *p3, *p4, *p5, *p6, *p7;
    cudaGetSymbolAddress(&p0, sc_hn);
    cudaGetSymbolAddress(&p1, sc_q);
    cudaGetSymbolAddress(&p2, sc_k);
    cudaGetSymbolAddress(&p3, sc_v);
    cudaGetSymbolAddress(&p4, sc_o);
    cudaGetSymbolAddress(&p5, sc_at);
    cudaGetSymbolAddress(&p6, sc_s);
    cudaGetSymbolAddress(&p7, sc_w);
    __half* hn = (__half*)p0;
    __half* q  = (__half*)p1;
    __half* k  = (__half*)p2;
    __half* v  = (__half*)p3;
    __half* o  = (__half*)p4;
    __half* at = (__half*)p5;
    float*  s  = (float*)p6;
    __half* wh = (__half*)p7;
    __half* whq = wh;
    __half* whk = wh + (size_t)CCH * CCH;
    __half* whv = wh + (size_t)2 * CCH * CCH;
    __half* whp = wh + (size_t)3 * CCH * CCH;

    const size_t sBC = (size_t)CCH * NTOK;
    const size_t sS  = (size_t)NTOK * NTOK;
    const int WBLK = CCH * CCH / 1024;

    cvt_w_kernel<<<WBLK, 256>>>(wq, whq);
    cvt_w_kernel<<<WBLK, 256>>>(wk, whk);
    cvt_w_kernel<<<WBLK, 256>>>(wv, whv);
    cvt_w_kernel<<<WBLK, 256>>>(wp, whp);

    groupnorm_kernel<<<dim3(NGRP, BATCH), 256>>>(x, gamma, beta, hn);

    // Q/K/V: C[oc][n] = sum_c W[oc][c] * hn[c][n]
    dim3 gQKV(NTOK / 128, CCH / 128, BATCH);
    hgemm<0, 1, true, false, true><<<gQKV, 256>>>(
        whq, hn, bq, nullptr, q, NTOK, CCH, CCH, NTOK, 0, sBC, sBC, 0, 1.f);
    hgemm<0, 1, true, false, true><<<gQKV, 256>>>(
        whk, hn, bk, nullptr, k, NTOK, CCH, CCH, NTOK, 0, sBC, sBC, 0, 1.f);
    hgemm<0, 1, true, false, true><<<gQKV, 256>>>(
        whv, hn, bv, nullptr, v, NTOK, CCH, CCH, NTOK, 0, sBC, sBC, 0, 1.f);

    // scores s[n][m] = scale * sum_c q[c][n] * k[c][m]
    dim3 gS(NTOK / 128, NTOK / 128, BATCH);
    hgemm<1, 1, false, false, false><<<gS, 256>>>(
        q, k, nullptr, nullptr, s, NTOK, CCH, NTOK, NTOK,
        sBC, sBC, sS, 0, 0.04419417382415922f);

    softmax_kernel<<<dim3(NTOK, BATCH), 256>>>(s, at);

    // o[c][n] = sum_m v[c][m] * attn[n][m]
    dim3 gAV(NTOK / 128, CCH / 128, BATCH);
    hgemm<0, 0, false, false, true><<<gAV, 256>>>(
        v, at, nullptr, nullptr, o, NTOK, NTOK, NTOK, NTOK, sBC, sS, sBC, 0, 1.f);

    // out = x + wp @ o + bp
    hgemm<0, 1, true, true, false><<<gQKV, 256>>>(
        whp, o, bp, x, out, NTOK, CCH, CCH, NTOK, 0, sBC, sBC, sBC, 1.f);
}

// round 9
// speedup vs baseline: 6.0220x; 1.4615x over previous
#include <cuda_runtime.h>
#include <cuda_fp16.h>
#include <cstdint>
#include <cstddef>

// ===========================================================================
// AttnBlock, fp16 mma.sync path, token-major intermediates, cp.async pipeline
// b=32, c=512, n=1024, groups=16
// Layouts: hn_T[b][n][512], qkv_T[b][n][1536] (q|k|v), s[b][n][m] f32,
//          at[b][n][m] f16, o_T[b][n][512], out[b][c][n] f32.
// ===========================================================================

#define BATCH 32
#define CCH   512
#define NTOK  1024
#define NGRP  16
#define CPG   (CCH / NGRP)
#define GSIZE (CPG * NTOK)

__device__ __half sc_hnT [(size_t)BATCH * NTOK * CCH];
__device__ __half sc_qkv [(size_t)BATCH * NTOK * 3 * CCH];
__device__ float  sc_s   [(size_t)BATCH * NTOK * NTOK];
__device__ __half sc_at  [(size_t)BATCH * NTOK * NTOK];
__device__ __half sc_oT  [(size_t)BATCH * NTOK * CCH];
__device__ __half sc_wcat[(size_t)3 * CCH * CCH];   // wq|wk|wv rows
__device__ __half sc_wp  [(size_t)CCH * CCH];
__device__ float  sc_bcat[3 * CCH];

// ---------------------------------------------------------------------------
// Smem operand: [row 0..127][kw 0..31] (kw = half-pair), pitch 36 words.
// ldmatrix conflict-free: 8 consecutive rows start at {0,4,8,...,28} mod 32,
// each 16B read then tiles all 32 banks.
// ---------------------------------------------------------------------------
#define PITCHW 36
#define OPW    (128 * PITCHW)              // 4608 words per operand buffer
#define GEMM_SMEM_BYTES (4 * OPW * 4)      // A0 B0 A1 B1 = 73728 B

__device__ __forceinline__ void cpa16(uint32_t saddr, const void* g) {
    asm volatile("cp.async.cg.shared.global [%0], [%1], 16;"
                 :: "r"(saddr), "l"(g));
}
#define CPA_COMMIT() asm volatile("cp.async.commit_group;" ::: "memory")
#define CPA_WAIT1()  asm volatile("cp.async.wait_group 1;" ::: "memory")
#define CPA_WAIT0()  asm volatile("cp.async.wait_group 0;" ::: "memory")

// TR0 tile via cp.async: 128 rows x 64 k halves (16 KB), 8x16B per row.
__device__ __forceinline__ void cpa_tile(uint32_t sbase_bytes,
                                         const __half* __restrict__ src,
                                         int ld, int row0, int k0, int t) {
    #pragma unroll
    for (int j = 0; j < 4; j++) {
        const int idx = t + 256 * j;
        const int r = idx >> 3, c8 = idx & 7;
        const void* g = src + (size_t)(row0 + r) * ld + k0 + c8 * 8;
        cpa16(sbase_bytes + (uint32_t)(r * PITCHW + c8 * 4) * 4u, g);
    }
}

// TR1 (transpose) staging for 64-k chunk: src is [k][row].
struct StageT { uint32_t w[16]; };
__device__ __forceinline__ StageT ldgT(const __half* __restrict__ src,
                                       int ld, int row0, int k0, int t) {
    StageT st;
    const int kp = t & 31, nb = t >> 5;
    const __half* p = src + (size_t)(k0 + 2 * kp) * ld + row0 + nb * 16;
    const uint4 u0 = *reinterpret_cast<const uint4*>(p);
    const uint4 u1 = *reinterpret_cast<const uint4*>(p + ld);
    const uint4 u2 = *reinterpret_cast<const uint4*>(p + 8);
    const uint4 u3 = *reinterpret_cast<const uint4*>(p + ld + 8);
    st.w[0] = u0.x; st.w[1] = u0.y; st.w[2]  = u0.z; st.w[3]  = u0.w;
    st.w[4] = u1.x; st.w[5] = u1.y; st.w[6]  = u1.z; st.w[7]  = u1.w;
    st.w[8] = u2.x; st.w[9] = u2.y; st.w[10] = u2.z; st.w[11] = u2.w;
    st.w[12] = u3.x; st.w[13] = u3.y; st.w[14] = u3.z; st.w[15] = u3.w;
    return st;
}
__device__ __forceinline__ void stsT(uint32_t* __restrict__ buf,
                                     const StageT& st, int t) {
    const int kp = t & 31, nb = t >> 5;
    #pragma unroll
    for (int e2 = 0; e2 < 4; e2++) {
        const uint32_t lo0 = __byte_perm(st.w[e2],     st.w[4 + e2],  0x5410);
        const uint32_t hi0 = __byte_perm(st.w[e2],     st.w[4 + e2],  0x7632);
        const uint32_t lo1 = __byte_perm(st.w[8 + e2], st.w[12 + e2], 0x5410);
        const uint32_t hi1 = __byte_perm(st.w[8 + e2], st.w[12 + e2], 0x7632);
        buf[(nb * 16 + 2 * e2 + 0) * PITCHW + kp] = lo0;
        buf[(nb * 16 + 2 * e2 + 1) * PITCHW + kp] = hi0;
        buf[(nb * 16 + 8 + 2 * e2 + 0) * PITCHW + kp] = lo1;
        buf[(nb * 16 + 8 + 2 * e2 + 1) * PITCHW + kp] = hi1;
    }
}

__device__ __forceinline__ void mma16816(float d[4], const uint32_t a[4],
                                         const uint32_t b[2]) {
    asm volatile(
        "mma.sync.aligned.m16n8k16.row.col.f32.f16.f16.f32 "
        "{%0,%1,%2,%3}, {%4,%5,%6,%7}, {%8,%9}, {%0,%1,%2,%3};"
        : "+f"(d[0]), "+f"(d[1]), "+f"(d[2]), "+f"(d[3])
        : "r"(a[0]), "r"(a[1]), "r"(a[2]), "r"(a[3]), "r"(b[0]), "r"(b[1]));
}
#define LDMX4(r0, r1, r2, r3, addr) \
    asm volatile("ldmatrix.sync.aligned.m8n8.x4.shared.b16 {%0,%1,%2,%3}, [%4];" \
                 : "=r"(r0), "=r"(r1), "=r"(r2), "=r"(r3) : "r"(addr))

// ---------------------------------------------------------------------------
// GEMM: C[m][n] = scale * sum_k A[m][k]*B'[n][k] (+bias) (+resid)
// A always row-major (cp.async). BT=0: B row-major [n][k] (cp.async);
// BT=1: B stored [k][n] (register transpose). BIASMODE 0/1(row)/2(col).
// 128x128x64 tile, 8 warps, double-buffered.
// ---------------------------------------------------------------------------
template<int BT, int BIASMODE, bool RESID, bool HOUT>
__global__ void __launch_bounds__(256, 2) hgemm(
    const __half* __restrict__ A, const __half* __restrict__ B,
    const float* __restrict__ bias, const float* __restrict__ resid,
    void* __restrict__ Cv, int N, int K, int ldA, int ldB,
    size_t sA, size_t sB, size_t sC, size_t sR, float scale)
{
    extern __shared__ __align__(16) uint32_t smbuf[];

    const int z = blockIdx.z;
    A += (size_t)z * sA;
    B += (size_t)z * sB;
    const float* R = RESID ? (resid + (size_t)z * sR) : nullptr;

    const int n0 = blockIdx.x * 128, m0 = blockIdx.y * 128;
    const int t = threadIdx.x;
    const int wid = t >> 5, lane = t & 31;
    const int wm = wid & 1, wn = wid >> 1;
    const int grp = lane >> 2, tig = lane & 3;

    const uint32_t smBase = (uint32_t)__cvta_generic_to_shared(smbuf);
    // buffers (byte offsets): A0=0, B0=OPW*4, A1=2*OPW*4, B1=3*OPW*4

    float acc[4][4][4] = {};
    StageT stB;

    // prologue: chunk 0
    cpa_tile(smBase, A, ldA, m0, 0, t);
    if (BT == 0) cpa_tile(smBase + OPW * 4, B, ldB, n0, 0, t);
    CPA_COMMIT();
    if (BT == 1) {
        stB = ldgT(B, ldB, n0, 0, t);
        stsT(smbuf + OPW, stB, t);
    }

    const uint32_t laneA =
        ((uint32_t)(wm * 64 + (lane & 7) + 8 * ((lane >> 3) & 1)) * PITCHW
         + 4u * ((lane >> 4) & 1)) * 4u;
    const uint32_t laneB =
        ((uint32_t)(wn * 32 + (lane & 7) + 8 * ((lane >> 4) & 1)) * PITCHW
         + 4u * ((lane >> 3) & 1)) * 4u;

    const int NK = K >> 6;
    for (int kc = 0; kc < NK; kc++) {
        const bool more = (kc + 1 < NK);
        const uint32_t cur = (kc & 1) ? (uint32_t)(2 * OPW * 4) : 0u;
        const uint32_t nxt = (kc & 1) ? 0u : (uint32_t)(2 * OPW * 4);
        if (more) {
            cpa_tile(smBase + nxt, A, ldA, m0, (kc + 1) * 64, t);
            if (BT == 0) cpa_tile(smBase + nxt + OPW * 4, B, ldB, n0, (kc + 1) * 64, t);
            CPA_COMMIT();
            if (BT == 1) stB = ldgT(B, ldB, n0, (kc + 1) * 64, t);
        }
        if (more) CPA_WAIT1(); else CPA_WAIT0();
        __syncthreads();

        const uint32_t aBuf = smBase + cur;
        const uint32_t bBuf = aBuf + (uint32_t)(OPW * 4);
        #pragma unroll
        for (int ks = 0; ks < 4; ks++) {
            uint32_t af[4][4], bf[4][2];
            #pragma unroll
            for (int mf = 0; mf < 4; mf++)
                LDMX4(af[mf][0], af[mf][1], af[mf][2], af[mf][3],
                      aBuf + laneA + (uint32_t)(mf * 16 * PITCHW * 4 + ks * 32));
            LDMX4(bf[0][0], bf[0][1], bf[1][0], bf[1][1],
                  bBuf + laneB + (uint32_t)(ks * 32));
            LDMX4(bf[2][0], bf[2][1], bf[3][0], bf[3][1],
                  bBuf + laneB + (uint32_t)(16 * PITCHW * 4 + ks * 32));
            #pragma unroll
            for (int mf = 0; mf < 4; mf++)
                #pragma unroll
                for (int nf = 0; nf < 4; nf++)
                    mma16816(acc[mf][nf], af[mf], bf[nf]);
        }
        if (BT == 1 && more) {
            uint32_t* nB = smbuf + (nxt >> 2) + OPW;
            stsT(nB, stB, t);
        }
        __syncthreads();
    }

    // ---- epilogue ----
    #pragma unroll
    for (int mf = 0; mf < 4; mf++) {
        const int r0 = m0 + wm * 64 + mf * 16 + grp;
        const float ba0 = (BIASMODE == 1) ? bias[r0] : 0.f;
        const float ba1 = (BIASMODE == 1) ? bias[r0 + 8] : 0.f;
        #pragma unroll
        for (int nf = 0; nf < 4; nf++) {
            const int cc = n0 + wn * 32 + nf * 8 + 2 * tig;
            float cb0 = 0.f, cb1 = 0.f;
            if (BIASMODE == 2) {
                const float2 cb = *reinterpret_cast<const float2*>(&bias[cc]);
                cb0 = cb.x; cb1 = cb.y;
            }
            float2 v0, v1;
            v0.x = acc[mf][nf][0] * scale + ba0 + cb0;
            v0.y = acc[mf][nf][1] * scale + ba0 + cb1;
            v1.x = acc[mf][nf][2] * scale + ba1 + cb0;
            v1.y = acc[mf][nf][3] * scale + ba1 + cb1;
            if (RESID) {
                const float2 q0 = *reinterpret_cast<const float2*>(&R[(size_t)r0 * N + cc]);
                const float2 q1 = *reinterpret_cast<const float2*>(&R[(size_t)(r0 + 8) * N + cc]);
                v0.x += q0.x; v0.y += q0.y;
                v1.x += q1.x; v1.y += q1.y;
            }
            if (HOUT) {
                __half* C = (__half*)Cv + (size_t)z * sC;
                *reinterpret_cast<__half2*>(&C[(size_t)r0 * N + cc]) =
                    __floats2half2_rn(v0.x, v0.y);
                *reinterpret_cast<__half2*>(&C[(size_t)(r0 + 8) * N + cc]) =
                    __floats2half2_rn(v1.x, v1.y);
            } else {
                float* C = (float*)Cv + (size_t)z * sC;
                *reinterpret_cast<float2*>(&C[(size_t)r0 * N + cc]) = v0;
                *reinterpret_cast<float2*>(&C[(size_t)(r0 + 8) * N + cc]) = v1;
            }
        }
    }
}

// ---------------------------------------------------------------------------
// Weight conversions: z in 0..3 picks (wq,wk,wv)->wcat rows, wp->sc_wp
// ---------------------------------------------------------------------------
__global__ void __launch_bounds__(256) cvt_w_kernel(
    const float* __restrict__ w0, const float* __restrict__ w1,
    const float* __restrict__ w2, const float* __restrict__ w3,
    __half* __restrict__ wcat, __half* __restrict__ wp)
{
    const int zz = blockIdx.y;
    const float* src = (zz == 0) ? w0 : (zz == 1) ? w1 : (zz == 2) ? w2 : w3;
    __half* dst = (zz == 3) ? wp : (wcat + (size_t)zz * CCH * CCH);
    const int i = blockIdx.x * 256 + threadIdx.x;
    const float4 v = reinterpret_cast<const float4*>(src)[i];
    __half2* d = reinterpret_cast<__half2*>(dst) + i * 2;
    d[0] = __floats2half2_rn(v.x, v.y);
    d[1] = __floats2half2_rn(v.z, v.w);
}

__global__ void __launch_bounds__(256) bcat_kernel(
    const float* __restrict__ b0, const float* __restrict__ b1,
    const float* __restrict__ b2, float* __restrict__ bcat)
{
    const int i = blockIdx.x * 256 + threadIdx.x;    // 0..1535
    bcat[i] = (i < 512) ? b0[i] : (i < 1024) ? b1[i - 512] : b2[i - 1024];
}

// ---------------------------------------------------------------------------
// GroupNorm -> token-major fp16: hn_T[b][token][c]
// ---------------------------------------------------------------------------
__global__ void __launch_bounds__(256) groupnorm_t_kernel(
    const float* __restrict__ x, const float* __restrict__ gamma,
    const float* __restrict__ beta, __half* __restrict__ hnT)
{
    const int g = blockIdx.x, b = blockIdx.y;
    const int c0 = g * CPG;
    const size_t xbase = ((size_t)b * CCH + c0) * NTOK;
    const int tid = threadIdx.x;

    // pass 1: stats
    const float4* xp = reinterpret_cast<const float4*>(x + xbase);
    float s = 0.f, ss = 0.f;
    for (int i = tid; i < GSIZE / 4; i += 256) {
        const float4 v = xp[i];
        s  += v.x + v.y + v.z + v.w;
        ss += v.x * v.x + v.y * v.y + v.z * v.z + v.w * v.w;
    }
    __shared__ float rs[256], rss[256];
    rs[tid] = s; rss[tid] = ss;
    __syncthreads();
    for (int w = 128; w > 0; w >>= 1) {
        if (tid < w) { rs[tid] += rs[tid + w]; rss[tid] += rss[tid + w]; }
        __syncthreads();
    }
    const float mean = rs[0] * (1.f / GSIZE);
    const float var  = rss[0] * (1.f / GSIZE) - mean * mean;
    const float rstd = rsqrtf(var + 1e-6f);

    __shared__ float gsc[CPG], gof[CPG];
    if (tid < CPG) {
        const float ga = gamma[c0 + tid] * rstd;
        gsc[tid] = ga;
        gof[tid] = beta[c0 + tid] - mean * ga;
    }
    __syncthreads();

    // pass 2: 4 tiles of 256 tokens, smem transpose, 64B/token writes
    __shared__ __half smh[32 * 264];
    for (int tt = 0; tt < 4; tt++) {
        const int tok0 = tt * 256;
        #pragma unroll 4
        for (int j = 0; j < 32; j++) {
            const float val = x[xbase + (size_t)j * NTOK + tok0 + tid];
            smh[j * 264 + tid] = __float2half(val * gsc[j] + gof[j]);
        }
        __syncthreads();
        const size_t obase = ((size_t)b * NTOK + tok0 + tid) * CCH + c0;
        __half2 wb[16];
        #pragma unroll
        for (int j2 = 0; j2 < 16; j2++) {
            const __half lo = smh[(2 * j2) * 264 + tid];
            const __half hi = smh[(2 * j2 + 1) * 264 + tid];
            wb[j2] = __halves2half2(lo, hi);
        }
        #pragma unroll
        for (int qd = 0; qd < 4; qd++) {
            *reinterpret_cast<uint4*>(&hnT[obase + qd * 8]) =
                *reinterpret_cast<const uint4*>(&wb[qd * 4]);
        }
        __syncthreads();
    }
}

// ---------------------------------------------------------------------------
// Row softmax: fp32 scores -> fp16 probs (per-row max == global shift)
// ---------------------------------------------------------------------------
__global__ void __launch_bounds__(256) softmax_kernel(
    const float* __restrict__ s, __half* __restrict__ attn)
{
    const size_t base = ((size_t)blockIdx.y * NTOK + blockIdx.x) * NTOK;
    const float4* p = reinterpret_cast<const float4*>(s + base);
    __half2*      o = reinterpret_cast<__half2*>(attn + base);
    const int tid = threadIdx.x;

    float4 v = p[tid];
    float m = fmaxf(fmaxf(v.x, v.y), fmaxf(v.z, v.w));

    __shared__ float red[256];
    red[tid] = m;
    __syncthreads();
    for (int w = 128; w > 0; w >>= 1) {
        if (tid < w) red[tid] = fmaxf(red[tid], red[tid + w]);
        __syncthreads();
    }
    m = red[0];
    __syncthreads();

    v.x = __expf(v.x - m); v.y = __expf(v.y - m);
    v.z = __expf(v.z - m); v.w = __expf(v.w - m);
    red[tid] = v.x + v.y + v.z + v.w;
    __syncthreads();
    for (int w = 128; w > 0; w >>= 1) {
        if (tid < w) red[tid] += red[tid + w];
        __syncthreads();
    }
    const float inv = 1.f / red[0];
    o[tid * 2 + 0] = __floats2half2_rn(v.x * inv, v.y * inv);
    o[tid * 2 + 1] = __floats2half2_rn(v.z * inv, v.w * inv);
}

// ---------------------------------------------------------------------------
extern "C" void kernel_launch(void* const* d_in, const int* in_sizes, int n_in,
                              void* d_out, int out_size)
{
    (void)in_sizes; (void)n_in; (void)out_size;
    const float* x     = (const float*)d_in[0];
    const float* gamma = (const float*)d_in[1];
    const float* beta  = (const float*)d_in[2];
    const float* wq    = (const float*)d_in[3];
    const float* bq    = (const float*)d_in[4];
    const float* wk    = (const float*)d_in[5];
    const float* bk    = (const float*)d_in[6];
    const float* wv    = (const float*)d_in[7];
    const float* bv    = (const float*)d_in[8];
    const float* wp    = (const float*)d_in[9];
    const float* bp    = (const float*)d_in[10];
    float* out = (float*)d_out;

    void *p0, *p1, *p2, *p3, *p4, *p5, *p6, *p7;
    cudaGetSymbolAddress(&p0, sc_hnT);
    cudaGetSymbolAddress(&p1, sc_qkv);
    cudaGetSymbolAddress(&p2, sc_s);
    cudaGetSymbolAddress(&p3, sc_at);
    cudaGetSymbolAddress(&p4, sc_oT);
    cudaGetSymbolAddress(&p5, sc_wcat);
    cudaGetSymbolAddress(&p6, sc_wp);
    cudaGetSymbolAddress(&p7, sc_bcat);
    __half* hnT  = (__half*)p0;
    __half* qkv  = (__half*)p1;
    float*  s    = (float*)p2;
    __half* at   = (__half*)p3;
    __half* oT   = (__half*)p4;
    __half* wcat = (__half*)p5;
    __half* whp  = (__half*)p6;
    float*  bcat = (float*)p7;

    const size_t sHN  = (size_t)NTOK * CCH;       // 524288
    const size_t sQKV = (size_t)NTOK * 3 * CCH;   // 1572864
    const size_t sS   = (size_t)NTOK * NTOK;

    cudaFuncSetAttribute(hgemm<0, 2, false, true>,
        cudaFuncAttributeMaxDynamicSharedMemorySize, GEMM_SMEM_BYTES);
    cudaFuncSetAttribute(hgemm<0, 0, false, false>,
        cudaFuncAttributeMaxDynamicSharedMemorySize, GEMM_SMEM_BYTES);
    cudaFuncSetAttribute(hgemm<1, 0, false, true>,
        cudaFuncAttributeMaxDynamicSharedMemorySize, GEMM_SMEM_BYTES);
    cudaFuncSetAttribute(hgemm<0, 1, true, false>,
        cudaFuncAttributeMaxDynamicSharedMemorySize, GEMM_SMEM_BYTES);

    cvt_w_kernel<<<dim3(256, 4), 256>>>(wq, wk, wv, wp, wcat, whp);
    bcat_kernel<<<6, 256>>>(bq, bk, bv, bcat);
    groupnorm_t_kernel<<<dim3(NGRP, BATCH), 256>>>(x, gamma, beta, hnT);

    // 1) fused QKV: qkv[token][oc'] = hnT[token][c] . wcat[oc'][c] + bcat[oc']
    hgemm<0, 2, false, true><<<dim3(12, 8, BATCH), 256, GEMM_SMEM_BYTES>>>(
        hnT, wcat, bcat, nullptr, qkv, 3 * CCH, CCH, CCH, CCH,
        sHN, 0, sQKV, 0, 1.f);

    // 2) scores s[n][m] = scale * q[n][:] . k[m][:]
    hgemm<0, 0, false, false><<<dim3(8, 8, BATCH), 256, GEMM_SMEM_BYTES>>>(
        qkv, qkv + CCH, nullptr, nullptr, s, NTOK, CCH, 3 * CCH, 3 * CCH,
        sQKV, sQKV, sS, 0, 0.04419417382415922f);

    // 3) softmax
    softmax_kernel<<<dim3(NTOK, BATCH), 256>>>(s, at);

    // 4) oT[n][c] = sum_m at[n][m] * v[m][c]   (B stored [m][c] -> TR1)
    hgemm<1, 0, false, true><<<dim3(4, 8, BATCH), 256, GEMM_SMEM_BYTES>>>(
        at, qkv + 2 * CCH, nullptr, nullptr, oT, CCH, NTOK, NTOK, 3 * CCH,
        sS, sQKV, sHN, 0, 1.f);

    // 5) out[oc][n] = x + wp[oc][:] . oT[n][:] + bp[oc]
    hgemm<0, 1, true, false><<<dim3(8, 4, BATCH), 256, GEMM_SMEM_BYTES>>>(
        whp, oT, bp, x, out, NTOK, CCH, CCH, CCH,
        0, sHN, sHN, sHN, 1.f);
}